// round 5
// baseline (speedup 1.0000x reference)
#include <cuda_runtime.h>

#define NN 50000          // nodes
#define NE 50000          // hyperedges
#define CH 128            // channels
#define NNZV 800000       // nnz
#define NT ((NN + 31) / 32)   // 1563 row tiles

// ---------------- scratch (device globals; float4-typed => 16B aligned) -----
__device__ float  g_w[NN];                        // sigmoid attention (per edge id)
__device__ float4 g_xl[(size_t)NN * 32];          // x @ lin_w^T   [row][32 x float4]
__device__ float4 g_ef[(size_t)NE * 32];          // edge features (Binv-scaled)
__device__ int    g_cntE[NE];
__device__ int    g_cntN[NN];
__device__ int    g_posE[NE];
__device__ int    g_posN[NN];
__device__ int    g_startE[NE + 1];
__device__ int    g_startN[NN + 1];
__device__ int    g_elist[NNZV];                  // node ids grouped by edge
__device__ int    g_nlist[NNZV];                  // edge ids grouped by node

// ---------------- kernel 0: zero counters ------------------------------------
__global__ void k_zero() {
    int i = blockIdx.x * blockDim.x + threadIdx.x;
    if (i < NE) { g_cntE[i] = 0; g_posE[i] = 0; }
    if (i < NN) { g_cntN[i] = 0; g_posN[i] = 0; }
}

// ---------------- kernel 1: xl = x @ lin_w^T, w = sigmoid(x·attn_w + b) -----
// 128 threads/block; static smem only (~35 KB). Each block owns one 32-channel
// chunk of lin_w (chunk = blockIdx & 3) and strides over row tiles.
__global__ void k_gemm(const float* __restrict__ x,
                       const float* __restrict__ lin_w,
                       const float* __restrict__ attn_w,
                       const float* __restrict__ attn_b) {
    __shared__ float s_lin[128 * 36];   // [k][c_local], pad 36
    __shared__ float s_x[32 * 129];     // [r][k]

    const int tid   = threadIdx.x;
    const int chunk = blockIdx.x & 3;          // which 32 output channels

    for (int idx = tid; idx < 128 * 32; idx += 128) {
        int k = idx >> 5, c = idx & 31;
        s_lin[k * 36 + c] = lin_w[(chunk * 32 + c) * 128 + k];
    }

    const int cg = tid & 7;     // 4-channel group within chunk
    const int rg = tid >> 3;    // 2-row group within tile

    for (int tile = blockIdx.x >> 2; tile < NT; tile += (gridDim.x >> 2)) {
        const int row0 = tile * 32;
        __syncthreads();
        for (int idx = tid; idx < 32 * 128; idx += 128) {
            int r = idx >> 7, k = idx & 127;
            int gr = row0 + r;
            s_x[r * 129 + k] = (gr < NN) ? x[(size_t)gr * CH + k] : 0.f;
        }
        __syncthreads();

        float4 a0 = make_float4(0.f, 0.f, 0.f, 0.f);
        float4 a1 = make_float4(0.f, 0.f, 0.f, 0.f);
#pragma unroll 4
        for (int k = 0; k < 128; k++) {
            float4 lw = *(const float4*)(s_lin + k * 36 + cg * 4);
            float x0 = s_x[(rg * 2 + 0) * 129 + k];
            float x1 = s_x[(rg * 2 + 1) * 129 + k];
            a0.x = fmaf(x0, lw.x, a0.x); a0.y = fmaf(x0, lw.y, a0.y);
            a0.z = fmaf(x0, lw.z, a0.z); a0.w = fmaf(x0, lw.w, a0.w);
            a1.x = fmaf(x1, lw.x, a1.x); a1.y = fmaf(x1, lw.y, a1.y);
            a1.z = fmaf(x1, lw.z, a1.z); a1.w = fmaf(x1, lw.w, a1.w);
        }
        int r0 = row0 + rg * 2;
        if (r0 < NN)     g_xl[(size_t)r0 * 32 + chunk * 8 + cg] = a0;
        if (r0 + 1 < NN) g_xl[(size_t)(r0 + 1) * 32 + chunk * 8 + cg] = a1;

        if (chunk == 0 && tid < 32) {
            int gr = row0 + tid;
            if (gr < NN) {
                float z = 0.f;
#pragma unroll 4
                for (int k = 0; k < 128; k++)
                    z = fmaf(s_x[tid * 129 + k], attn_w[k], z);
                z += attn_b[0];
                g_w[gr] = 1.f / (1.f + __expf(-z));
            }
        }
    }
}

// ---------------- kernel 2: histogram (degrees) ------------------------------
// he is INT32: he[0..NNZV) = node ids, he[NNZV..2*NNZV) = edge ids
__global__ void k_hist(const int* __restrict__ he) {
    int i = blockIdx.x * blockDim.x + threadIdx.x;
    if (i >= NNZV) return;
    unsigned n = (unsigned)he[i];
    unsigned e = (unsigned)he[NNZV + i];
    if (e < NE) atomicAdd(&g_cntE[e], 1);
    if (n < NN) atomicAdd(&g_cntN[n], 1);
}

// ---------------- kernel 3: exclusive scans (2 blocks, 1024 thr) -------------
__global__ void k_scan() {
    const int* cnt  = (blockIdx.x == 0) ? g_cntE : g_cntN;
    int*       strt = (blockIdx.x == 0) ? g_startE : g_startN;
    const int  len  = (blockIdx.x == 0) ? NE : NN;

    __shared__ int part[1024];
    const int t = threadIdx.x;
    const int CHUNK = 49;              // 1024*49 >= 50000
    const int base = t * CHUNK;

    int s = 0;
    for (int i = 0; i < CHUNK; i++) {
        int idx = base + i;
        if (idx < len) s += cnt[idx];
    }
    part[t] = s;
    __syncthreads();
    for (int off = 1; off < 1024; off <<= 1) {
        int v = (t >= off) ? part[t - off] : 0;
        __syncthreads();
        part[t] += v;
        __syncthreads();
    }
    int run = (t > 0) ? part[t - 1] : 0;
    for (int i = 0; i < CHUNK; i++) {
        int idx = base + i;
        if (idx < len) { strt[idx] = run; run += cnt[idx]; }
    }
    if (t == 1023) strt[len] = run;
}

// ---------------- kernel 4: fill CSR adjacency lists -------------------------
__global__ void k_fill(const int* __restrict__ he) {
    int i = blockIdx.x * blockDim.x + threadIdx.x;
    if (i >= NNZV) return;
    unsigned n = (unsigned)he[i];
    unsigned e = (unsigned)he[NNZV + i];
    if (n >= NN || e >= NE) return;
    int sl = atomicAdd(&g_posE[e], 1);
    g_elist[g_startE[e] + sl] = (int)n;
    sl = atomicAdd(&g_posN[n], 1);
    g_nlist[g_startN[n] + sl] = (int)e;
}

// ---------------- kernel 5: edge gather: ef[e] = Binv * sum xl[n] ------------
// warp per edge; lane = one float4 (4 channels)
__global__ void k_gather_edge() {
    int e    = (blockIdx.x * blockDim.x + threadIdx.x) >> 5;
    int lane = threadIdx.x & 31;
    if (e >= NE) return;
    int s   = g_startE[e];
    int end = g_startE[e + 1];
    float4 acc = make_float4(0.f, 0.f, 0.f, 0.f);
    for (int j = s; j < end; j++) {
        int n = g_elist[j];
        float4 v = g_xl[(size_t)n * 32 + lane];
        acc.x += v.x; acc.y += v.y; acc.z += v.z; acc.w += v.w;
    }
    float binv = (end > s) ? (1.f / (float)(end - s)) : 0.f;
    acc.x *= binv; acc.y *= binv; acc.z *= binv; acc.w *= binv;
    g_ef[(size_t)e * 32 + lane] = acc;
}

// ---------------- kernel 6: node gather + Dinv + bias ------------------------
__global__ void k_gather_node(float* __restrict__ out,
                              const float* __restrict__ bias) {
    int n    = (blockIdx.x * blockDim.x + threadIdx.x) >> 5;
    int lane = threadIdx.x & 31;
    if (n >= NN) return;
    int s   = g_startN[n];
    int end = g_startN[n + 1];
    float4 acc = make_float4(0.f, 0.f, 0.f, 0.f);
    float dsum = 0.f;
    for (int j = s; j < end; j++) {
        int e = g_nlist[j];
        dsum += g_w[e];
        float4 v = g_ef[(size_t)e * 32 + lane];
        acc.x += v.x; acc.y += v.y; acc.z += v.z; acc.w += v.w;
    }
    float dinv = (dsum > 0.f) ? (1.f / dsum) : 0.f;
    float bx = bias[lane * 4 + 0], by = bias[lane * 4 + 1];
    float bz = bias[lane * 4 + 2], bw = bias[lane * 4 + 3];
    float* op = out + (size_t)n * CH + lane * 4;
    op[0] = fmaf(acc.x, dinv, bx);
    op[1] = fmaf(acc.y, dinv, by);
    op[2] = fmaf(acc.z, dinv, bz);
    op[3] = fmaf(acc.w, dinv, bw);
}

// ---------------- launch -----------------------------------------------------
extern "C" void kernel_launch(void* const* d_in, const int* in_sizes, int n_in,
                              void* d_out, int out_size) {
    const float* x      = (const float*)d_in[0];     // [50000,128] f32
    const int*   he     = (const int*)d_in[1];       // [2,800000] int32 (JAX x64 off)
    const float* attn_w = (const float*)d_in[2];     // [1,128]
    const float* attn_b = (const float*)d_in[3];     // [1]
    const float* lin_w  = (const float*)d_in[4];     // [128,128]
    const float* bias   = (const float*)d_in[5];     // [128]
    float*       out    = (float*)d_out;             // [50000,128]

    k_zero<<<(NE + 255) / 256, 256>>>();

    k_gemm<<<296, 128>>>(x, lin_w, attn_w, attn_b);   // 4 chunks x 74 blocks

    const int nb = (NNZV + 255) / 256;
    k_hist<<<nb, 256>>>(he);
    k_scan<<<2, 1024>>>();
    k_fill<<<nb, 256>>>(he);

    const int gb = (NE * 32 + 255) / 256;   // warp per edge/node
    k_gather_edge<<<gb, 256>>>();
    k_gather_node<<<gb, 256>>>(out, bias);
}

// round 6
// speedup vs baseline: 1.8000x; 1.8000x over previous
#include <cuda_runtime.h>

#define NN 50000          // nodes
#define NE 50000          // hyperedges
#define CH 128            // channels
#define NNZV 800000       // nnz
#define NBE 196           // ceil(50000/256) blocks per scan domain
#define TOTB (2 * NBE)    // 392

// ---------------- scratch (device globals) -----------------------------------
__device__ float  g_w[NN];                        // sigmoid attention (per edge id)
__device__ float4 g_xl[(size_t)NN * 32];          // x @ lin_w^T   [row][32 x float4]
__device__ float4 g_ef[(size_t)NE * 32];          // edge features (Binv-scaled)
__device__ int    g_cntE[NE];
__device__ int    g_cntN[NN];
__device__ int    g_posE[NE];                     // absolute fill cursors
__device__ int    g_posN[NN];
__device__ int    g_startE[NE + 1];
__device__ int    g_startN[NN + 1];
__device__ int    g_elist[NNZV];                  // node ids grouped by edge
__device__ int    g_nlist[NNZV];                  // edge ids grouped by node
__device__ int    g_blksum[TOTB];
__device__ int    g_blkoff[TOTB];

// ---------------- kernel 0: zero counters ------------------------------------
__global__ void k_zero() {
    int i = blockIdx.x * blockDim.x + threadIdx.x;
    if (i < NE) g_cntE[i] = 0;
    if (i < NN) g_cntN[i] = 0;
}

// ---------------- kernel 1: xl = x @ lin_w^T, w = sigmoid(x·attn_w + b) -----
// 128 threads; dynamic smem: lin_w transposed [128][132] + x tile [32][129].
// x is read exactly once across the grid.
__global__ void k_gemm(const float* __restrict__ x,
                       const float* __restrict__ lin_w,
                       const float* __restrict__ attn_w,
                       const float* __restrict__ attn_b) {
    extern __shared__ float sm[];
    float* s_lin = sm;                 // [k][c] stride 132
    float* s_x   = sm + 128 * 132;     // [r][k] stride 129

    const int tid = threadIdx.x;
    for (int idx = tid; idx < CH * CH; idx += 128) {
        int c = idx >> 7, k = idx & 127;
        s_lin[k * 132 + c] = lin_w[idx];          // transpose
    }

    const int cg = tid & 31;   // channels [4*cg, 4*cg+3]
    const int rg = tid >> 5;   // rows [8*rg, 8*rg+7] of the tile

    const int ntiles = (NN + 31) / 32;
    for (int tile = blockIdx.x; tile < ntiles; tile += gridDim.x) {
        const int row0 = tile * 32;
        __syncthreads();   // protects s_x readers of prev tile (and s_lin, iter 0)
        for (int idx = tid; idx < 32 * CH; idx += 128) {
            int r = idx >> 7, k = idx & 127;
            int gr = row0 + r;
            s_x[r * 129 + k] = (gr < NN) ? x[(size_t)gr * CH + k] : 0.f;
        }
        __syncthreads();

        float4 acc[8];
#pragma unroll
        for (int r = 0; r < 8; r++) acc[r] = make_float4(0.f, 0.f, 0.f, 0.f);

#pragma unroll 4
        for (int k = 0; k < CH; k++) {
            float4 lw = *(const float4*)(s_lin + k * 132 + cg * 4);
#pragma unroll
            for (int r = 0; r < 8; r++) {
                float xv = s_x[(rg * 8 + r) * 129 + k];
                acc[r].x = fmaf(xv, lw.x, acc[r].x);
                acc[r].y = fmaf(xv, lw.y, acc[r].y);
                acc[r].z = fmaf(xv, lw.z, acc[r].z);
                acc[r].w = fmaf(xv, lw.w, acc[r].w);
            }
        }
#pragma unroll
        for (int r = 0; r < 8; r++) {
            int gr = row0 + rg * 8 + r;
            if (gr < NN) g_xl[(size_t)gr * 32 + cg] = acc[r];
        }

        if (tid < 32) {
            int gr = row0 + tid;
            if (gr < NN) {
                float z = 0.f;
#pragma unroll 4
                for (int k = 0; k < CH; k++)
                    z = fmaf(s_x[tid * 129 + k], attn_w[k], z);
                z += attn_b[0];
                g_w[gr] = 1.f / (1.f + __expf(-z));
            }
        }
    }
}

// ---------------- kernel 2: histogram (degrees) ------------------------------
__global__ void k_hist(const int* __restrict__ he) {
    int i = blockIdx.x * blockDim.x + threadIdx.x;
    if (i >= NNZV) return;
    unsigned n = (unsigned)he[i];
    unsigned e = (unsigned)he[NNZV + i];
    if (e < NE) atomicAdd(&g_cntE[e], 1);
    if (n < NN) atomicAdd(&g_cntN[n], 1);
}

// ---------------- scan phase A: per-block sums -------------------------------
__global__ void k_scanA() {
    const int bid = blockIdx.x;
    const bool isE = bid < NBE;
    const int lb   = isE ? bid : bid - NBE;
    const int base = lb * 256 + threadIdx.x;
    const int* cnt = isE ? g_cntE : g_cntN;
    const int len  = isE ? NE : NN;

    int v = (base < len) ? cnt[base] : 0;
#pragma unroll
    for (int off = 16; off > 0; off >>= 1)
        v += __shfl_down_sync(0xffffffffu, v, off);
    __shared__ int ws[8];
    if ((threadIdx.x & 31) == 0) ws[threadIdx.x >> 5] = v;
    __syncthreads();
    if (threadIdx.x == 0) {
        int s = 0;
#pragma unroll
        for (int w = 0; w < 8; w++) s += ws[w];
        g_blksum[bid] = s;
    }
}

// ---------------- scan phase B: scan the 2x196 partials ----------------------
__global__ void k_scanB() {
    __shared__ int s[512];
    const int t = threadIdx.x;
    const int half = t >> 8, i = t & 255;
    const int idx = half * NBE + i;
    int v0 = (i < NBE) ? g_blksum[idx] : 0;
    s[t] = v0;
    __syncthreads();
#pragma unroll
    for (int off = 1; off < 256; off <<= 1) {
        int v = (i >= off) ? s[half * 256 + i - off] : 0;
        __syncthreads();
        s[t] += v;
        __syncthreads();
    }
    if (i < NBE) g_blkoff[idx] = s[t] - v0;   // exclusive
}

// ---------------- scan phase C: local scan + write starts & cursors ----------
__global__ void k_scanC() {
    const int bid = blockIdx.x;
    const bool isE = bid < NBE;
    const int lb   = isE ? bid : bid - NBE;
    const int base = lb * 256 + threadIdx.x;
    const int* cnt = isE ? g_cntE : g_cntN;
    int* strt = isE ? g_startE : g_startN;
    int* pos  = isE ? g_posE   : g_posN;
    const int len  = isE ? NE : NN;

    __shared__ int s[256];
    const int t = threadIdx.x;
    int c = (base < len) ? cnt[base] : 0;
    s[t] = c;
    __syncthreads();
#pragma unroll
    for (int off = 1; off < 256; off <<= 1) {
        int v = (t >= off) ? s[t - off] : 0;
        __syncthreads();
        s[t] += v;
        __syncthreads();
    }
    int excl = s[t] - c + g_blkoff[bid];
    if (base < len) { strt[base] = excl; pos[base] = excl; }
    if (base == len - 1) strt[len] = excl + c;
}

// ---------------- kernel 4: fill CSR adjacency lists (absolute cursors) ------
__global__ void k_fill(const int* __restrict__ he) {
    int i = blockIdx.x * blockDim.x + threadIdx.x;
    if (i >= NNZV) return;
    unsigned n = (unsigned)he[i];
    unsigned e = (unsigned)he[NNZV + i];
    if (n >= NN || e >= NE) return;
    g_elist[atomicAdd(&g_posE[e], 1)] = (int)n;
    g_nlist[atomicAdd(&g_posN[n], 1)] = (int)e;
}

// ---------------- kernel 5: edge gather: ef[e] = Binv * sum xl[n] ------------
// warp per edge; lane = one float4 (4 channels); 4-way batched for MLP
__global__ void k_gather_edge() {
    int e    = (blockIdx.x * blockDim.x + threadIdx.x) >> 5;
    int lane = threadIdx.x & 31;
    if (e >= NE) return;
    int s   = g_startE[e];
    int end = g_startE[e + 1];
    float4 acc = make_float4(0.f, 0.f, 0.f, 0.f);
    int j = s;
    for (; j + 4 <= end; j += 4) {
        int n0 = g_elist[j], n1 = g_elist[j + 1];
        int n2 = g_elist[j + 2], n3 = g_elist[j + 3];
        float4 v0 = g_xl[(size_t)n0 * 32 + lane];
        float4 v1 = g_xl[(size_t)n1 * 32 + lane];
        float4 v2 = g_xl[(size_t)n2 * 32 + lane];
        float4 v3 = g_xl[(size_t)n3 * 32 + lane];
        acc.x += v0.x + v1.x + v2.x + v3.x;
        acc.y += v0.y + v1.y + v2.y + v3.y;
        acc.z += v0.z + v1.z + v2.z + v3.z;
        acc.w += v0.w + v1.w + v2.w + v3.w;
    }
    for (; j < end; j++) {
        int n = g_elist[j];
        float4 v = g_xl[(size_t)n * 32 + lane];
        acc.x += v.x; acc.y += v.y; acc.z += v.z; acc.w += v.w;
    }
    float binv = (end > s) ? (1.f / (float)(end - s)) : 0.f;
    acc.x *= binv; acc.y *= binv; acc.z *= binv; acc.w *= binv;
    g_ef[(size_t)e * 32 + lane] = acc;
}

// ---------------- kernel 6: node gather + Dinv + bias ------------------------
__global__ void k_gather_node(float* __restrict__ out,
                              const float* __restrict__ bias) {
    int n    = (blockIdx.x * blockDim.x + threadIdx.x) >> 5;
    int lane = threadIdx.x & 31;
    if (n >= NN) return;
    int s   = g_startN[n];
    int end = g_startN[n + 1];
    float4 acc = make_float4(0.f, 0.f, 0.f, 0.f);
    float dsum = 0.f;
    int j = s;
    for (; j + 4 <= end; j += 4) {
        int e0 = g_nlist[j], e1 = g_nlist[j + 1];
        int e2 = g_nlist[j + 2], e3 = g_nlist[j + 3];
        float4 v0 = g_ef[(size_t)e0 * 32 + lane];
        float4 v1 = g_ef[(size_t)e1 * 32 + lane];
        float4 v2 = g_ef[(size_t)e2 * 32 + lane];
        float4 v3 = g_ef[(size_t)e3 * 32 + lane];
        dsum += g_w[e0] + g_w[e1] + g_w[e2] + g_w[e3];
        acc.x += v0.x + v1.x + v2.x + v3.x;
        acc.y += v0.y + v1.y + v2.y + v3.y;
        acc.z += v0.z + v1.z + v2.z + v3.z;
        acc.w += v0.w + v1.w + v2.w + v3.w;
    }
    for (; j < end; j++) {
        int e = g_nlist[j];
        dsum += g_w[e];
        float4 v = g_ef[(size_t)e * 32 + lane];
        acc.x += v.x; acc.y += v.y; acc.z += v.z; acc.w += v.w;
    }
    float dinv = (dsum > 0.f) ? (1.f / dsum) : 0.f;
    float bx = bias[lane * 4 + 0], by = bias[lane * 4 + 1];
    float bz = bias[lane * 4 + 2], bw = bias[lane * 4 + 3];
    float* op = out + (size_t)n * CH + lane * 4;
    op[0] = fmaf(acc.x, dinv, bx);
    op[1] = fmaf(acc.y, dinv, by);
    op[2] = fmaf(acc.z, dinv, bz);
    op[3] = fmaf(acc.w, dinv, bw);
}

// ---------------- launch -----------------------------------------------------
extern "C" void kernel_launch(void* const* d_in, const int* in_sizes, int n_in,
                              void* d_out, int out_size) {
    const float* x      = (const float*)d_in[0];     // [50000,128] f32
    const int*   he     = (const int*)d_in[1];       // [2,800000] int32
    const float* attn_w = (const float*)d_in[2];     // [1,128]
    const float* attn_b = (const float*)d_in[3];     // [1]
    const float* lin_w  = (const float*)d_in[4];     // [128,128]
    const float* bias   = (const float*)d_in[5];     // [128]
    float*       out    = (float*)d_out;             // [50000,128]

    k_zero<<<(NE + 255) / 256, 256>>>();

    const int smem = (128 * 132 + 32 * 129) * (int)sizeof(float);  // ~82 KB
    cudaFuncSetAttribute(k_gemm, cudaFuncAttributeMaxDynamicSharedMemorySize, smem);
    k_gemm<<<296, 128, smem>>>(x, lin_w, attn_w, attn_b);

    const int nb = (NNZV + 255) / 256;
    k_hist<<<nb, 256>>>(he);
    k_scanA<<<TOTB, 256>>>();
    k_scanB<<<1, 512>>>();
    k_scanC<<<TOTB, 256>>>();
    k_fill<<<nb, 256>>>(he);

    const int gb = (NE * 32 + 255) / 256;   // warp per edge/node
    k_gather_edge<<<gb, 256>>>();
    k_gather_node<<<gb, 256>>>(out, bias);
}

// round 7
// speedup vs baseline: 2.0536x; 1.1409x over previous
#include <cuda_runtime.h>
#include <cuda_fp16.h>

#define NN 50000          // nodes
#define NE 50000          // hyperedges
#define CH 128            // channels
#define NNZV 800000       // nnz
#define NBE 196           // ceil(50000/256) blocks per scan domain
#define TOTB (2 * NBE)    // 392

// ---------------- scratch (device globals) -----------------------------------
__device__ float  g_w[NN];                        // sigmoid attention (per edge id)
__device__ __half g_xlh[(size_t)NN * CH];         // x @ lin_w^T  (fp16)
__device__ __half g_efh[(size_t)NE * CH];         // edge features (fp16, Binv-scaled)
__device__ int    g_cntE[NE];
__device__ int    g_cntN[NN];
__device__ int    g_posE[NE];                     // absolute fill cursors
__device__ int    g_posN[NN];
__device__ int    g_startE[NE + 1];
__device__ int    g_startN[NN + 1];
__device__ int    g_elist[NNZV];                  // node ids grouped by edge
__device__ int    g_nlist[NNZV];                  // edge ids grouped by node
__device__ int    g_blksum[TOTB];
__device__ int    g_blkoff[TOTB];

// ---------------- kernel 0: zero counters ------------------------------------
__global__ void k_zero() {
    int i = blockIdx.x * blockDim.x + threadIdx.x;
    if (i < NE) g_cntE[i] = 0;
    if (i < NN) g_cntN[i] = 0;
}

// ---------------- kernel 1: xl = x @ lin_w^T (fp16 out), w = sigmoid(...) ---
// 128 threads; dynamic smem: s_lin [k][c] stride 132 + s_x [k][r] stride 34.
// Inner loop uses packed fma.rn.f32x2: row-pairs are native f32x2 operands.
__global__ void k_gemm(const float* __restrict__ x,
                       const float* __restrict__ lin_w,
                       const float* __restrict__ attn_w,
                       const float* __restrict__ attn_b) {
    extern __shared__ float sm[];
    float* s_lin = sm;                 // [k][c] stride 132
    float* s_x   = sm + 128 * 132;     // [k][r] stride 34 (transposed tile)

    const int tid = threadIdx.x;
    for (int idx = tid; idx < CH * CH; idx += 128) {
        int c = idx >> 7, k = idx & 127;
        s_lin[k * 132 + c] = lin_w[idx];          // transpose
    }

    const int cg = tid & 31;   // channels [4*cg, 4*cg+3]
    const int rg = tid >> 5;   // rows [8*rg, 8*rg+7] of the tile

    const int ntiles = (NN + 31) / 32;
    for (int tile = blockIdx.x; tile < ntiles; tile += gridDim.x) {
        const int row0 = tile * 32;
        __syncthreads();   // protects s_x readers of prev tile (and s_lin, iter 0)
        // coalesced global read, transposed smem write: s_x[k][r]
        for (int idx = tid; idx < 32 * CH; idx += 128) {
            int r = idx >> 7, k = idx & 127;
            int gr = row0 + r;
            s_x[k * 34 + r] = (gr < NN) ? x[(size_t)gr * CH + k] : 0.f;
        }
        __syncthreads();

        unsigned long long acc[4][4];   // [row-pair][channel], f32x2 packed
#pragma unroll
        for (int p = 0; p < 4; p++)
#pragma unroll
            for (int c = 0; c < 4; c++) acc[p][c] = 0ull;

#pragma unroll 4
        for (int k = 0; k < CH; k++) {
            const float4 w4 = *(const float4*)(s_lin + k * 132 + cg * 4);
            unsigned long long bw[4];
            asm("mov.b64 %0, {%1, %1};" : "=l"(bw[0]) : "f"(w4.x));
            asm("mov.b64 %0, {%1, %1};" : "=l"(bw[1]) : "f"(w4.y));
            asm("mov.b64 %0, {%1, %1};" : "=l"(bw[2]) : "f"(w4.z));
            asm("mov.b64 %0, {%1, %1};" : "=l"(bw[3]) : "f"(w4.w));
            const unsigned long long* xp =
                (const unsigned long long*)(s_x + k * 34 + rg * 8);
#pragma unroll
            for (int p = 0; p < 4; p++) {
                unsigned long long a = xp[p];
#pragma unroll
                for (int c = 0; c < 4; c++)
                    asm("fma.rn.f32x2 %0, %1, %2, %3;"
                        : "=l"(acc[p][c]) : "l"(a), "l"(bw[c]), "l"(acc[p][c]));
            }
        }

        // epilogue: unpack, convert to fp16, store 4 channels per row
#pragma unroll
        for (int p = 0; p < 4; p++) {
            float r0v[4], r1v[4];
#pragma unroll
            for (int c = 0; c < 4; c++)
                asm("mov.b64 {%0, %1}, %2;"
                    : "=f"(r0v[c]), "=f"(r1v[c]) : "l"(acc[p][c]));
            int r0 = row0 + rg * 8 + 2 * p;
            if (r0 < NN) {
                __half2 h0 = __floats2half2_rn(r0v[0], r0v[1]);
                __half2 h1 = __floats2half2_rn(r0v[2], r0v[3]);
                *(__half2*)(g_xlh + (size_t)r0 * CH + cg * 4)     = h0;
                *(__half2*)(g_xlh + (size_t)r0 * CH + cg * 4 + 2) = h1;
            }
            if (r0 + 1 < NN) {
                __half2 h0 = __floats2half2_rn(r1v[0], r1v[1]);
                __half2 h1 = __floats2half2_rn(r1v[2], r1v[3]);
                *(__half2*)(g_xlh + (size_t)(r0 + 1) * CH + cg * 4)     = h0;
                *(__half2*)(g_xlh + (size_t)(r0 + 1) * CH + cg * 4 + 2) = h1;
            }
        }

        // attention weights: warp 0, one row per lane (s_x is [k][r] now)
        if (tid < 32) {
            int gr = row0 + tid;
            if (gr < NN) {
                float z = 0.f;
#pragma unroll 4
                for (int k = 0; k < CH; k++)
                    z = fmaf(s_x[k * 34 + tid], attn_w[k], z);
                z += attn_b[0];
                g_w[gr] = 1.f / (1.f + __expf(-z));
            }
        }
    }
}

// ---------------- kernel 2: histogram (degrees) ------------------------------
__global__ void k_hist(const int* __restrict__ he) {
    int i = blockIdx.x * blockDim.x + threadIdx.x;
    if (i >= NNZV) return;
    unsigned n = (unsigned)he[i];
    unsigned e = (unsigned)he[NNZV + i];
    if (e < NE) atomicAdd(&g_cntE[e], 1);
    if (n < NN) atomicAdd(&g_cntN[n], 1);
}

// ---------------- scan phase A: per-block sums -------------------------------
__global__ void k_scanA() {
    const int bid = blockIdx.x;
    const bool isE = bid < NBE;
    const int lb   = isE ? bid : bid - NBE;
    const int base = lb * 256 + threadIdx.x;
    const int* cnt = isE ? g_cntE : g_cntN;
    const int len  = isE ? NE : NN;

    int v = (base < len) ? cnt[base] : 0;
#pragma unroll
    for (int off = 16; off > 0; off >>= 1)
        v += __shfl_down_sync(0xffffffffu, v, off);
    __shared__ int ws[8];
    if ((threadIdx.x & 31) == 0) ws[threadIdx.x >> 5] = v;
    __syncthreads();
    if (threadIdx.x == 0) {
        int s = 0;
#pragma unroll
        for (int w = 0; w < 8; w++) s += ws[w];
        g_blksum[bid] = s;
    }
}

// ---------------- scan phase B: scan the 2x196 partials ----------------------
__global__ void k_scanB() {
    __shared__ int s[512];
    const int t = threadIdx.x;
    const int half = t >> 8, i = t & 255;
    const int idx = half * NBE + i;
    int v0 = (i < NBE) ? g_blksum[idx] : 0;
    s[t] = v0;
    __syncthreads();
#pragma unroll
    for (int off = 1; off < 256; off <<= 1) {
        int v = (i >= off) ? s[half * 256 + i - off] : 0;
        __syncthreads();
        s[t] += v;
        __syncthreads();
    }
    if (i < NBE) g_blkoff[idx] = s[t] - v0;   // exclusive
}

// ---------------- scan phase C: local scan + write starts & cursors ----------
__global__ void k_scanC() {
    const int bid = blockIdx.x;
    const bool isE = bid < NBE;
    const int lb   = isE ? bid : bid - NBE;
    const int base = lb * 256 + threadIdx.x;
    const int* cnt = isE ? g_cntE : g_cntN;
    int* strt = isE ? g_startE : g_startN;
    int* pos  = isE ? g_posE   : g_posN;
    const int len  = isE ? NE : NN;

    __shared__ int s[256];
    const int t = threadIdx.x;
    int c = (base < len) ? cnt[base] : 0;
    s[t] = c;
    __syncthreads();
#pragma unroll
    for (int off = 1; off < 256; off <<= 1) {
        int v = (t >= off) ? s[t - off] : 0;
        __syncthreads();
        s[t] += v;
        __syncthreads();
    }
    int excl = s[t] - c + g_blkoff[bid];
    if (base < len) { strt[base] = excl; pos[base] = excl; }
    if (base == len - 1) strt[len] = excl + c;
}

// ---------------- kernel 4: fill CSR adjacency lists (absolute cursors) ------
__global__ void k_fill(const int* __restrict__ he) {
    int i = blockIdx.x * blockDim.x + threadIdx.x;
    if (i >= NNZV) return;
    unsigned n = (unsigned)he[i];
    unsigned e = (unsigned)he[NNZV + i];
    if (n >= NN || e >= NE) return;
    g_elist[atomicAdd(&g_posE[e], 1)] = (int)n;
    g_nlist[atomicAdd(&g_posN[n], 1)] = (int)e;
}

// fp16 row accumulate helper: 4 channels per lane, 8 bytes per row
__device__ __forceinline__ void acc_h4(float4& acc, const __half* row, int lane) {
    uint2 raw = *(const uint2*)(row + lane * 4);
    __half2 h0 = *(__half2*)&raw.x;
    __half2 h1 = *(__half2*)&raw.y;
    float2 f0 = __half22float2(h0);
    float2 f1 = __half22float2(h1);
    acc.x += f0.x; acc.y += f0.y; acc.z += f1.x; acc.w += f1.y;
}

// ---------------- kernel 5: edge gather: ef[e] = Binv * sum xl[n] ------------
// warp per edge; lane = 4 channels (8 B fp16); 4-way batched for MLP
__global__ void k_gather_edge() {
    int e    = (blockIdx.x * blockDim.x + threadIdx.x) >> 5;
    int lane = threadIdx.x & 31;
    if (e >= NE) return;
    int s   = g_startE[e];
    int end = g_startE[e + 1];
    float4 acc = make_float4(0.f, 0.f, 0.f, 0.f);
    int j = s;
    for (; j + 4 <= end; j += 4) {
        int n0 = g_elist[j], n1 = g_elist[j + 1];
        int n2 = g_elist[j + 2], n3 = g_elist[j + 3];
        acc_h4(acc, g_xlh + (size_t)n0 * CH, lane);
        acc_h4(acc, g_xlh + (size_t)n1 * CH, lane);
        acc_h4(acc, g_xlh + (size_t)n2 * CH, lane);
        acc_h4(acc, g_xlh + (size_t)n3 * CH, lane);
    }
    for (; j < end; j++)
        acc_h4(acc, g_xlh + (size_t)g_elist[j] * CH, lane);

    float binv = (end > s) ? (1.f / (float)(end - s)) : 0.f;
    __half2 h0 = __floats2half2_rn(acc.x * binv, acc.y * binv);
    __half2 h1 = __floats2half2_rn(acc.z * binv, acc.w * binv);
    uint2 raw;
    raw.x = *(unsigned*)&h0;
    raw.y = *(unsigned*)&h1;
    *(uint2*)(g_efh + (size_t)e * CH + lane * 4) = raw;
}

// ---------------- kernel 6: node gather + Dinv + bias ------------------------
__global__ void k_gather_node(float* __restrict__ out,
                              const float* __restrict__ bias) {
    int n    = (blockIdx.x * blockDim.x + threadIdx.x) >> 5;
    int lane = threadIdx.x & 31;
    if (n >= NN) return;
    int s   = g_startN[n];
    int end = g_startN[n + 1];
    float4 acc = make_float4(0.f, 0.f, 0.f, 0.f);
    float dsum = 0.f;
    int j = s;
    for (; j + 4 <= end; j += 4) {
        int e0 = g_nlist[j], e1 = g_nlist[j + 1];
        int e2 = g_nlist[j + 2], e3 = g_nlist[j + 3];
        dsum += g_w[e0] + g_w[e1] + g_w[e2] + g_w[e3];
        acc_h4(acc, g_efh + (size_t)e0 * CH, lane);
        acc_h4(acc, g_efh + (size_t)e1 * CH, lane);
        acc_h4(acc, g_efh + (size_t)e2 * CH, lane);
        acc_h4(acc, g_efh + (size_t)e3 * CH, lane);
    }
    for (; j < end; j++) {
        int e = g_nlist[j];
        dsum += g_w[e];
        acc_h4(acc, g_efh + (size_t)e * CH, lane);
    }
    float dinv = (dsum > 0.f) ? (1.f / dsum) : 0.f;
    float bx = bias[lane * 4 + 0], by = bias[lane * 4 + 1];
    float bz = bias[lane * 4 + 2], bw = bias[lane * 4 + 3];
    float* op = out + (size_t)n * CH + lane * 4;
    op[0] = fmaf(acc.x, dinv, bx);
    op[1] = fmaf(acc.y, dinv, by);
    op[2] = fmaf(acc.z, dinv, bz);
    op[3] = fmaf(acc.w, dinv, bw);
}

// ---------------- launch -----------------------------------------------------
extern "C" void kernel_launch(void* const* d_in, const int* in_sizes, int n_in,
                              void* d_out, int out_size) {
    const float* x      = (const float*)d_in[0];     // [50000,128] f32
    const int*   he     = (const int*)d_in[1];       // [2,800000] int32
    const float* attn_w = (const float*)d_in[2];     // [1,128]
    const float* attn_b = (const float*)d_in[3];     // [1]
    const float* lin_w  = (const float*)d_in[4];     // [128,128]
    const float* bias   = (const float*)d_in[5];     // [128]
    float*       out    = (float*)d_out;             // [50000,128]

    k_zero<<<(NE + 255) / 256, 256>>>();

    const int smem = (128 * 132 + 128 * 34) * (int)sizeof(float);  // ~85 KB
    cudaFuncSetAttribute(k_gemm, cudaFuncAttributeMaxDynamicSharedMemorySize, smem);
    k_gemm<<<296, 128, smem>>>(x, lin_w, attn_w, attn_b);

    const int nb = (NNZV + 255) / 256;
    k_hist<<<nb, 256>>>(he);
    k_scanA<<<TOTB, 256>>>();
    k_scanB<<<1, 512>>>();
    k_scanC<<<TOTB, 256>>>();
    k_fill<<<nb, 256>>>(he);

    const int gb = (NE * 32 + 255) / 256;   // warp per edge/node
    k_gather_edge<<<gb, 256>>>();
    k_gather_node<<<gb, 256>>>(out, bias);
}

// round 8
// speedup vs baseline: 2.0852x; 1.0154x over previous
#include <cuda_runtime.h>
#include <cuda_fp16.h>

#define NN 50000          // nodes
#define NE 50000          // hyperedges
#define CH 128            // channels
#define NNZV 800000       // nnz
#define NBE 196           // ceil(50000/256) blocks per scan domain
#define TOTB (2 * NBE)    // 392

// ---------------- scratch (device globals) -----------------------------------
__device__ float  g_w[NN];                        // sigmoid attention (per edge id)
__device__ __half g_xlh[(size_t)NN * CH];         // x @ lin_w^T  (fp16)
__device__ __half g_efh[(size_t)NE * CH];         // edge features (fp16, Binv-scaled)
__device__ int    g_cntE[NE];
__device__ int    g_cntN[NN];
__device__ int    g_posE[NE];                     // absolute fill cursors
__device__ int    g_posN[NN];
__device__ int    g_startE[NE + 1];
__device__ int    g_startN[NN + 1];
__device__ int    g_elist[NNZV];                  // node ids grouped by edge
__device__ int    g_nlist[NNZV];                  // edge ids grouped by node
__device__ int    g_blksum[TOTB];
__device__ int    g_blkoff[TOTB];

// ---------------- kernel 0: zero counters ------------------------------------
__global__ void k_zero() {
    int i = blockIdx.x * blockDim.x + threadIdx.x;
    if (i < NE) g_cntE[i] = 0;
    if (i < NN) g_cntN[i] = 0;
}

// ---------------- kernel 1: xl = x @ lin_w^T (fp16 out), w = sigmoid(...) ---
__global__ void k_gemm(const float* __restrict__ x,
                       const float* __restrict__ lin_w,
                       const float* __restrict__ attn_w,
                       const float* __restrict__ attn_b) {
    extern __shared__ float sm[];
    float* s_lin = sm;                 // [k][c] stride 132
    float* s_x   = sm + 128 * 132;     // [k][r] stride 34 (transposed tile)

    const int tid = threadIdx.x;
    for (int idx = tid; idx < CH * CH; idx += 128) {
        int c = idx >> 7, k = idx & 127;
        s_lin[k * 132 + c] = lin_w[idx];          // transpose
    }

    const int cg = tid & 31;   // channels [4*cg, 4*cg+3]
    const int rg = tid >> 5;   // rows [8*rg, 8*rg+7] of the tile

    const int ntiles = (NN + 31) / 32;
    for (int tile = blockIdx.x; tile < ntiles; tile += gridDim.x) {
        const int row0 = tile * 32;
        __syncthreads();
        for (int idx = tid; idx < 32 * CH; idx += 128) {
            int r = idx >> 7, k = idx & 127;
            int gr = row0 + r;
            s_x[k * 34 + r] = (gr < NN) ? x[(size_t)gr * CH + k] : 0.f;
        }
        __syncthreads();

        unsigned long long acc[4][4];   // [row-pair][channel], f32x2 packed
#pragma unroll
        for (int p = 0; p < 4; p++)
#pragma unroll
            for (int c = 0; c < 4; c++) acc[p][c] = 0ull;

#pragma unroll 4
        for (int k = 0; k < CH; k++) {
            const float4 w4 = *(const float4*)(s_lin + k * 132 + cg * 4);
            unsigned long long bw[4];
            asm("mov.b64 %0, {%1, %1};" : "=l"(bw[0]) : "f"(w4.x));
            asm("mov.b64 %0, {%1, %1};" : "=l"(bw[1]) : "f"(w4.y));
            asm("mov.b64 %0, {%1, %1};" : "=l"(bw[2]) : "f"(w4.z));
            asm("mov.b64 %0, {%1, %1};" : "=l"(bw[3]) : "f"(w4.w));
            const unsigned long long* xp =
                (const unsigned long long*)(s_x + k * 34 + rg * 8);
#pragma unroll
            for (int p = 0; p < 4; p++) {
                unsigned long long a = xp[p];
#pragma unroll
                for (int c = 0; c < 4; c++)
                    asm("fma.rn.f32x2 %0, %1, %2, %3;"
                        : "=l"(acc[p][c]) : "l"(a), "l"(bw[c]), "l"(acc[p][c]));
            }
        }

#pragma unroll
        for (int p = 0; p < 4; p++) {
            float r0v[4], r1v[4];
#pragma unroll
            for (int c = 0; c < 4; c++)
                asm("mov.b64 {%0, %1}, %2;"
                    : "=f"(r0v[c]), "=f"(r1v[c]) : "l"(acc[p][c]));
            int r0 = row0 + rg * 8 + 2 * p;
            if (r0 < NN) {
                __half2 h0 = __floats2half2_rn(r0v[0], r0v[1]);
                __half2 h1 = __floats2half2_rn(r0v[2], r0v[3]);
                *(__half2*)(g_xlh + (size_t)r0 * CH + cg * 4)     = h0;
                *(__half2*)(g_xlh + (size_t)r0 * CH + cg * 4 + 2) = h1;
            }
            if (r0 + 1 < NN) {
                __half2 h0 = __floats2half2_rn(r1v[0], r1v[1]);
                __half2 h1 = __floats2half2_rn(r1v[2], r1v[3]);
                *(__half2*)(g_xlh + (size_t)(r0 + 1) * CH + cg * 4)     = h0;
                *(__half2*)(g_xlh + (size_t)(r0 + 1) * CH + cg * 4 + 2) = h1;
            }
        }

        if (tid < 32) {
            int gr = row0 + tid;
            if (gr < NN) {
                float z = 0.f;
#pragma unroll 4
                for (int k = 0; k < CH; k++)
                    z = fmaf(s_x[k * 34 + tid], attn_w[k], z);
                z += attn_b[0];
                g_w[gr] = 1.f / (1.f + __expf(-z));
            }
        }
    }
}

// ---------------- kernel 2: histogram (degrees) ------------------------------
__global__ void k_hist(const int* __restrict__ he) {
    int i = blockIdx.x * blockDim.x + threadIdx.x;
    if (i >= NNZV) return;
    unsigned n = (unsigned)he[i];
    unsigned e = (unsigned)he[NNZV + i];
    if (e < NE) atomicAdd(&g_cntE[e], 1);
    if (n < NN) atomicAdd(&g_cntN[n], 1);
}

// ---------------- scan phase A: per-block sums -------------------------------
__global__ void k_scanA() {
    const int bid = blockIdx.x;
    const bool isE = bid < NBE;
    const int lb   = isE ? bid : bid - NBE;
    const int base = lb * 256 + threadIdx.x;
    const int* cnt = isE ? g_cntE : g_cntN;
    const int len  = isE ? NE : NN;

    int v = (base < len) ? cnt[base] : 0;
#pragma unroll
    for (int off = 16; off > 0; off >>= 1)
        v += __shfl_down_sync(0xffffffffu, v, off);
    __shared__ int ws[8];
    if ((threadIdx.x & 31) == 0) ws[threadIdx.x >> 5] = v;
    __syncthreads();
    if (threadIdx.x == 0) {
        int s = 0;
#pragma unroll
        for (int w = 0; w < 8; w++) s += ws[w];
        g_blksum[bid] = s;
    }
}

// ---------------- scan phase B: scan the 2x196 partials ----------------------
__global__ void k_scanB() {
    __shared__ int s[512];
    const int t = threadIdx.x;
    const int half = t >> 8, i = t & 255;
    const int idx = half * NBE + i;
    int v0 = (i < NBE) ? g_blksum[idx] : 0;
    s[t] = v0;
    __syncthreads();
#pragma unroll
    for (int off = 1; off < 256; off <<= 1) {
        int v = (i >= off) ? s[half * 256 + i - off] : 0;
        __syncthreads();
        s[t] += v;
        __syncthreads();
    }
    if (i < NBE) g_blkoff[idx] = s[t] - v0;   // exclusive
}

// ---------------- scan phase C: local scan + write starts & cursors ----------
__global__ void k_scanC() {
    const int bid = blockIdx.x;
    const bool isE = bid < NBE;
    const int lb   = isE ? bid : bid - NBE;
    const int base = lb * 256 + threadIdx.x;
    const int* cnt = isE ? g_cntE : g_cntN;
    int* strt = isE ? g_startE : g_startN;
    int* pos  = isE ? g_posE   : g_posN;
    const int len  = isE ? NE : NN;

    __shared__ int s[256];
    const int t = threadIdx.x;
    int c = (base < len) ? cnt[base] : 0;
    s[t] = c;
    __syncthreads();
#pragma unroll
    for (int off = 1; off < 256; off <<= 1) {
        int v = (t >= off) ? s[t - off] : 0;
        __syncthreads();
        s[t] += v;
        __syncthreads();
    }
    int excl = s[t] - c + g_blkoff[bid];
    if (base < len) { strt[base] = excl; pos[base] = excl; }
    if (base == len - 1) strt[len] = excl + c;
}

// ---------------- kernel 4: fill CSR adjacency lists (absolute cursors) ------
__global__ void k_fill(const int* __restrict__ he) {
    int i = blockIdx.x * blockDim.x + threadIdx.x;
    if (i >= NNZV) return;
    unsigned n = (unsigned)he[i];
    unsigned e = (unsigned)he[NNZV + i];
    if (n >= NN || e >= NE) return;
    g_elist[atomicAdd(&g_posE[e], 1)] = (int)n;
    g_nlist[atomicAdd(&g_posN[n], 1)] = (int)e;
}

// accumulate 8 fp16 channels (16 B) into 8 fp32 accumulators
__device__ __forceinline__ void acc_h8(float4& a0, float4& a1, const __half* p) {
    uint4 raw = *(const uint4*)p;
    float2 f0 = __half22float2(*(__half2*)&raw.x);
    float2 f1 = __half22float2(*(__half2*)&raw.y);
    float2 f2 = __half22float2(*(__half2*)&raw.z);
    float2 f3 = __half22float2(*(__half2*)&raw.w);
    a0.x += f0.x; a0.y += f0.y; a0.z += f1.x; a0.w += f1.y;
    a1.x += f2.x; a1.y += f2.y; a1.z += f3.x; a1.w += f3.y;
}

// ---------------- kernel 5: edge gather: ef[e] = Binv * sum xl[n] ------------
// HALF-warp per edge: 16 lanes x 16 B (8 channels); 4-way batched
__global__ void k_gather_edge() {
    int warp = (blockIdx.x * blockDim.x + threadIdx.x) >> 5;
    int lane = threadIdx.x & 31;
    int sub  = lane & 15;                 // 8-channel chunk
    int e = warp * 2 + (lane >> 4);
    if (e >= NE) return;
    int s   = g_startE[e];
    int end = g_startE[e + 1];
    float4 a0 = make_float4(0.f, 0.f, 0.f, 0.f);
    float4 a1 = make_float4(0.f, 0.f, 0.f, 0.f);
    const __half* base = g_xlh + sub * 8;
    int j = s;
    for (; j + 4 <= end; j += 4) {
        int n0 = g_elist[j],     n1 = g_elist[j + 1];
        int n2 = g_elist[j + 2], n3 = g_elist[j + 3];
        acc_h8(a0, a1, base + (size_t)n0 * CH);
        acc_h8(a0, a1, base + (size_t)n1 * CH);
        acc_h8(a0, a1, base + (size_t)n2 * CH);
        acc_h8(a0, a1, base + (size_t)n3 * CH);
    }
    for (; j < end; j++)
        acc_h8(a0, a1, base + (size_t)g_elist[j] * CH);

    float binv = (end > s) ? (1.f / (float)(end - s)) : 0.f;
    uint4 raw;
    __half2 h;
    h = __floats2half2_rn(a0.x * binv, a0.y * binv); raw.x = *(unsigned*)&h;
    h = __floats2half2_rn(a0.z * binv, a0.w * binv); raw.y = *(unsigned*)&h;
    h = __floats2half2_rn(a1.x * binv, a1.y * binv); raw.z = *(unsigned*)&h;
    h = __floats2half2_rn(a1.z * binv, a1.w * binv); raw.w = *(unsigned*)&h;
    *(uint4*)(g_efh + (size_t)e * CH + sub * 8) = raw;
}

// ---------------- kernel 6: node gather + Dinv + bias ------------------------
// HALF-warp per node: 16 lanes x 16 B; 4-way batched
__global__ void k_gather_node(float* __restrict__ out,
                              const float* __restrict__ bias) {
    int warp = (blockIdx.x * blockDim.x + threadIdx.x) >> 5;
    int lane = threadIdx.x & 31;
    int sub  = lane & 15;
    int n = warp * 2 + (lane >> 4);
    if (n >= NN) return;
    int s   = g_startN[n];
    int end = g_startN[n + 1];
    float4 a0 = make_float4(0.f, 0.f, 0.f, 0.f);
    float4 a1 = make_float4(0.f, 0.f, 0.f, 0.f);
    float dsum = 0.f;
    const __half* base = g_efh + sub * 8;
    int j = s;
    for (; j + 4 <= end; j += 4) {
        int e0 = g_nlist[j],     e1 = g_nlist[j + 1];
        int e2 = g_nlist[j + 2], e3 = g_nlist[j + 3];
        dsum += __ldg(&g_w[e0]) + __ldg(&g_w[e1]) + __ldg(&g_w[e2]) + __ldg(&g_w[e3]);
        acc_h8(a0, a1, base + (size_t)e0 * CH);
        acc_h8(a0, a1, base + (size_t)e1 * CH);
        acc_h8(a0, a1, base + (size_t)e2 * CH);
        acc_h8(a0, a1, base + (size_t)e3 * CH);
    }
    for (; j < end; j++) {
        int e = g_nlist[j];
        dsum += __ldg(&g_w[e]);
        acc_h8(a0, a1, base + (size_t)e * CH);
    }
    float dinv = (dsum > 0.f) ? (1.f / dsum) : 0.f;
    float4 b0 = *(const float4*)(bias + sub * 8);
    float4 b1 = *(const float4*)(bias + sub * 8 + 4);
    float* op = out + (size_t)n * CH + sub * 8;
    op[0] = fmaf(a0.x, dinv, b0.x);
    op[1] = fmaf(a0.y, dinv, b0.y);
    op[2] = fmaf(a0.z, dinv, b0.z);
    op[3] = fmaf(a0.w, dinv, b0.w);
    op[4] = fmaf(a1.x, dinv, b1.x);
    op[5] = fmaf(a1.y, dinv, b1.y);
    op[6] = fmaf(a1.z, dinv, b1.z);
    op[7] = fmaf(a1.w, dinv, b1.w);
}

// ---------------- launch -----------------------------------------------------
extern "C" void kernel_launch(void* const* d_in, const int* in_sizes, int n_in,
                              void* d_out, int out_size) {
    const float* x      = (const float*)d_in[0];     // [50000,128] f32
    const int*   he     = (const int*)d_in[1];       // [2,800000] int32
    const float* attn_w = (const float*)d_in[2];     // [1,128]
    const float* attn_b = (const float*)d_in[3];     // [1]
    const float* lin_w  = (const float*)d_in[4];     // [128,128]
    const float* bias   = (const float*)d_in[5];     // [128]
    float*       out    = (float*)d_out;             // [50000,128]

    k_zero<<<(NE + 255) / 256, 256>>>();

    const int smem = (128 * 132 + 128 * 34) * (int)sizeof(float);  // ~85 KB
    cudaFuncSetAttribute(k_gemm, cudaFuncAttributeMaxDynamicSharedMemorySize, smem);
    k_gemm<<<296, 128, smem>>>(x, lin_w, attn_w, attn_b);

    const int nb = (NNZV + 255) / 256;
    k_hist<<<nb, 256>>>(he);
    k_scanA<<<TOTB, 256>>>();
    k_scanB<<<1, 512>>>();
    k_scanC<<<TOTB, 256>>>();
    k_fill<<<nb, 256>>>(he);

    // half-warp per row: NE/2 warps per gather
    const int gb = ((NE / 2) * 32 + 255) / 256;
    k_gather_edge<<<gb, 256>>>();
    k_gather_node<<<gb, 256>>>(out, bias);
}

// round 9
// speedup vs baseline: 2.2363x; 1.0724x over previous
#include <cuda_runtime.h>
#include <cuda_fp16.h>

#define NN 50000          // nodes
#define NE 50000          // hyperedges
#define CH 128            // channels
#define NNZV 800000       // nnz
#define NBE 196           // ceil(50000/256) blocks per scan domain
#define TOTB (2 * NBE)    // 392

// ---------------- scratch (device globals) -----------------------------------
__device__ float  g_w[NN];                        // sigmoid attention (per edge id)
__device__ __half g_xlh[(size_t)NN * CH];         // x @ lin_w^T  (fp16)
__device__ __half g_efh[(size_t)NE * CH];         // edge features (fp16, Binv-scaled)
__device__ int    g_cntE[NE];
__device__ int    g_cntN[NN];
__device__ int    g_posE[NE];                     // absolute fill cursors
__device__ int    g_posN[NN];
__device__ int    g_startE[NE + 1];
__device__ int    g_startN[NN + 1];
__device__ int    g_elist[NNZV];                  // node ids grouped by edge
__device__ int    g_nlist[NNZV];                  // edge ids grouped by node
__device__ int    g_blksum[TOTB];

// ---------------- kernel 0: zero counters ------------------------------------
__global__ void k_zero() {
    int i = blockIdx.x * blockDim.x + threadIdx.x;
    if (i < NE) g_cntE[i] = 0;
    if (i < NN) g_cntN[i] = 0;
}

// ---------------- kernel 1: xl = x @ lin_w^T (fp16 out), w = sigmoid(...) ---
__global__ void k_gemm(const float* __restrict__ x,
                       const float* __restrict__ lin_w,
                       const float* __restrict__ attn_w,
                       const float* __restrict__ attn_b) {
    extern __shared__ float sm[];
    float* s_lin = sm;                 // [k][c] stride 132
    float* s_x   = sm + 128 * 132;     // [k][r] stride 34 (transposed tile)

    const int tid = threadIdx.x;
    for (int idx = tid; idx < CH * CH; idx += 128) {
        int c = idx >> 7, k = idx & 127;
        s_lin[k * 132 + c] = lin_w[idx];          // transpose
    }

    const int cg = tid & 31;   // channels [4*cg, 4*cg+3]
    const int rg = tid >> 5;   // rows [8*rg, 8*rg+7] of the tile

    const int ntiles = (NN + 31) / 32;
    for (int tile = blockIdx.x; tile < ntiles; tile += gridDim.x) {
        const int row0 = tile * 32;
        __syncthreads();
        for (int idx = tid; idx < 32 * CH; idx += 128) {
            int r = idx >> 7, k = idx & 127;
            int gr = row0 + r;
            s_x[k * 34 + r] = (gr < NN) ? x[(size_t)gr * CH + k] : 0.f;
        }
        __syncthreads();

        unsigned long long acc[4][4];   // [row-pair][channel], f32x2 packed
#pragma unroll
        for (int p = 0; p < 4; p++)
#pragma unroll
            for (int c = 0; c < 4; c++) acc[p][c] = 0ull;

#pragma unroll 4
        for (int k = 0; k < CH; k++) {
            const float4 w4 = *(const float4*)(s_lin + k * 132 + cg * 4);
            unsigned long long bw[4];
            asm("mov.b64 %0, {%1, %1};" : "=l"(bw[0]) : "f"(w4.x));
            asm("mov.b64 %0, {%1, %1};" : "=l"(bw[1]) : "f"(w4.y));
            asm("mov.b64 %0, {%1, %1};" : "=l"(bw[2]) : "f"(w4.z));
            asm("mov.b64 %0, {%1, %1};" : "=l"(bw[3]) : "f"(w4.w));
            const unsigned long long* xp =
                (const unsigned long long*)(s_x + k * 34 + rg * 8);
#pragma unroll
            for (int p = 0; p < 4; p++) {
                unsigned long long a = xp[p];
#pragma unroll
                for (int c = 0; c < 4; c++)
                    asm("fma.rn.f32x2 %0, %1, %2, %3;"
                        : "=l"(acc[p][c]) : "l"(a), "l"(bw[c]), "l"(acc[p][c]));
            }
        }

#pragma unroll
        for (int p = 0; p < 4; p++) {
            float r0v[4], r1v[4];
#pragma unroll
            for (int c = 0; c < 4; c++)
                asm("mov.b64 {%0, %1}, %2;"
                    : "=f"(r0v[c]), "=f"(r1v[c]) : "l"(acc[p][c]));
            int r0 = row0 + rg * 8 + 2 * p;
            if (r0 < NN) {
                __half2 h0 = __floats2half2_rn(r0v[0], r0v[1]);
                __half2 h1 = __floats2half2_rn(r0v[2], r0v[3]);
                *(__half2*)(g_xlh + (size_t)r0 * CH + cg * 4)     = h0;
                *(__half2*)(g_xlh + (size_t)r0 * CH + cg * 4 + 2) = h1;
            }
            if (r0 + 1 < NN) {
                __half2 h0 = __floats2half2_rn(r1v[0], r1v[1]);
                __half2 h1 = __floats2half2_rn(r1v[2], r1v[3]);
                *(__half2*)(g_xlh + (size_t)(r0 + 1) * CH + cg * 4)     = h0;
                *(__half2*)(g_xlh + (size_t)(r0 + 1) * CH + cg * 4 + 2) = h1;
            }
        }

        if (tid < 32) {
            int gr = row0 + tid;
            if (gr < NN) {
                float z = 0.f;
#pragma unroll 4
                for (int k = 0; k < CH; k++)
                    z = fmaf(s_x[k * 34 + tid], attn_w[k], z);
                z += attn_b[0];
                g_w[gr] = 1.f / (1.f + __expf(-z));
            }
        }
    }
}

// ---------------- kernel 2: histogram (degrees) ------------------------------
__global__ void k_hist(const int* __restrict__ he) {
    int i = blockIdx.x * blockDim.x + threadIdx.x;
    if (i >= NNZV) return;
    unsigned n = (unsigned)he[i];
    unsigned e = (unsigned)he[NNZV + i];
    if (e < NE) atomicAdd(&g_cntE[e], 1);
    if (n < NN) atomicAdd(&g_cntN[n], 1);
}

// ---------------- scan phase A: per-block sums -------------------------------
__global__ void k_scanA() {
    const int bid = blockIdx.x;
    const bool isE = bid < NBE;
    const int lb   = isE ? bid : bid - NBE;
    const int base = lb * 256 + threadIdx.x;
    const int* cnt = isE ? g_cntE : g_cntN;
    const int len  = isE ? NE : NN;

    int v = (base < len) ? cnt[base] : 0;
#pragma unroll
    for (int off = 16; off > 0; off >>= 1)
        v += __shfl_down_sync(0xffffffffu, v, off);
    __shared__ int ws[8];
    if ((threadIdx.x & 31) == 0) ws[threadIdx.x >> 5] = v;
    __syncthreads();
    if (threadIdx.x == 0) {
        int s = 0;
#pragma unroll
        for (int w = 0; w < 8; w++) s += ws[w];
        g_blksum[bid] = s;
    }
}

// ---------------- scan phase C: block prefix + local scan + starts/cursors ---
__global__ void k_scanC() {
    const int bid = blockIdx.x;
    const bool isE = bid < NBE;
    const int lb   = isE ? bid : bid - NBE;
    const int base = lb * 256 + threadIdx.x;
    const int* cnt = isE ? g_cntE : g_cntN;
    int* strt = isE ? g_startE : g_startN;
    int* pos  = isE ? g_posE   : g_posN;
    const int len  = isE ? NE : NN;
    const int t = threadIdx.x;

    // block offset = sum of g_blksum for preceding blocks in this half
    __shared__ int ws[8];
    __shared__ int s_off;
    int pre = (t < lb) ? g_blksum[(isE ? 0 : NBE) + t] : 0;
#pragma unroll
    for (int off = 16; off > 0; off >>= 1)
        pre += __shfl_down_sync(0xffffffffu, pre, off);
    if ((t & 31) == 0) ws[t >> 5] = pre;
    __syncthreads();
    if (t == 0) {
        int s = 0;
#pragma unroll
        for (int w = 0; w < 8; w++) s += ws[w];
        s_off = s;
    }
    __syncthreads();

    // local Hillis-Steele scan of this block's 256 counts
    __shared__ int s[256];
    int c = (base < len) ? cnt[base] : 0;
    s[t] = c;
    __syncthreads();
#pragma unroll
    for (int off = 1; off < 256; off <<= 1) {
        int v = (t >= off) ? s[t - off] : 0;
        __syncthreads();
        s[t] += v;
        __syncthreads();
    }
    int excl = s[t] - c + s_off;
    if (base < len) { strt[base] = excl; pos[base] = excl; }
    if (base == len - 1) strt[len] = excl + c;
}

// ---------------- kernel 4: fill CSR adjacency lists (absolute cursors) ------
__global__ void k_fill(const int* __restrict__ he) {
    int i = blockIdx.x * blockDim.x + threadIdx.x;
    if (i >= NNZV) return;
    unsigned n = (unsigned)he[i];
    unsigned e = (unsigned)he[NNZV + i];
    if (n >= NN || e >= NE) return;
    g_elist[atomicAdd(&g_posE[e], 1)] = (int)n;
    g_nlist[atomicAdd(&g_posN[n], 1)] = (int)e;
}

// accumulate 8 fp16 channels (16 B) into 8 fp32 accumulators
__device__ __forceinline__ void acc_h8(float4& a0, float4& a1, const __half* p) {
    uint4 raw = *(const uint4*)p;
    float2 f0 = __half22float2(*(__half2*)&raw.x);
    float2 f1 = __half22float2(*(__half2*)&raw.y);
    float2 f2 = __half22float2(*(__half2*)&raw.z);
    float2 f3 = __half22float2(*(__half2*)&raw.w);
    a0.x += f0.x; a0.y += f0.y; a0.z += f1.x; a0.w += f1.y;
    a1.x += f2.x; a1.y += f2.y; a1.z += f3.x; a1.w += f3.y;
}

// ---------------- kernel 5: edge gather: ef[e] = Binv * sum xl[n] ------------
// HALF-warp per edge: 16 lanes x 16 B (8 channels); 4-way batched
__global__ void k_gather_edge() {
    int warp = (blockIdx.x * blockDim.x + threadIdx.x) >> 5;
    int lane = threadIdx.x & 31;
    int sub  = lane & 15;                 // 8-channel chunk
    int e = warp * 2 + (lane >> 4);
    if (e >= NE) return;
    int s   = g_startE[e];
    int end = g_startE[e + 1];
    float4 a0 = make_float4(0.f, 0.f, 0.f, 0.f);
    float4 a1 = make_float4(0.f, 0.f, 0.f, 0.f);
    const __half* base = g_xlh + sub * 8;
    int j = s;
    for (; j + 4 <= end; j += 4) {
        int n0 = g_elist[j],     n1 = g_elist[j + 1];
        int n2 = g_elist[j + 2], n3 = g_elist[j + 3];
        acc_h8(a0, a1, base + (size_t)n0 * CH);
        acc_h8(a0, a1, base + (size_t)n1 * CH);
        acc_h8(a0, a1, base + (size_t)n2 * CH);
        acc_h8(a0, a1, base + (size_t)n3 * CH);
    }
    for (; j < end; j++)
        acc_h8(a0, a1, base + (size_t)g_elist[j] * CH);

    float binv = (end > s) ? (1.f / (float)(end - s)) : 0.f;
    uint4 raw;
    __half2 h;
    h = __floats2half2_rn(a0.x * binv, a0.y * binv); raw.x = *(unsigned*)&h;
    h = __floats2half2_rn(a0.z * binv, a0.w * binv); raw.y = *(unsigned*)&h;
    h = __floats2half2_rn(a1.x * binv, a1.y * binv); raw.z = *(unsigned*)&h;
    h = __floats2half2_rn(a1.z * binv, a1.w * binv); raw.w = *(unsigned*)&h;
    *(uint4*)(g_efh + (size_t)e * CH + sub * 8) = raw;
}

// ---------------- kernel 6: node gather + Dinv + bias ------------------------
// HALF-warp per node: 16 lanes x 16 B; 4-way batched
__global__ void k_gather_node(float* __restrict__ out,
                              const float* __restrict__ bias) {
    int warp = (blockIdx.x * blockDim.x + threadIdx.x) >> 5;
    int lane = threadIdx.x & 31;
    int sub  = lane & 15;
    int n = warp * 2 + (lane >> 4);
    if (n >= NN) return;
    int s   = g_startN[n];
    int end = g_startN[n + 1];
    float4 a0 = make_float4(0.f, 0.f, 0.f, 0.f);
    float4 a1 = make_float4(0.f, 0.f, 0.f, 0.f);
    float dsum = 0.f;
    const __half* base = g_efh + sub * 8;
    int j = s;
    for (; j + 4 <= end; j += 4) {
        int e0 = g_nlist[j],     e1 = g_nlist[j + 1];
        int e2 = g_nlist[j + 2], e3 = g_nlist[j + 3];
        dsum += __ldg(&g_w[e0]) + __ldg(&g_w[e1]) + __ldg(&g_w[e2]) + __ldg(&g_w[e3]);
        acc_h8(a0, a1, base + (size_t)e0 * CH);
        acc_h8(a0, a1, base + (size_t)e1 * CH);
        acc_h8(a0, a1, base + (size_t)e2 * CH);
        acc_h8(a0, a1, base + (size_t)e3 * CH);
    }
    for (; j < end; j++) {
        int e = g_nlist[j];
        dsum += __ldg(&g_w[e]);
        acc_h8(a0, a1, base + (size_t)e * CH);
    }
    float dinv = (dsum > 0.f) ? (1.f / dsum) : 0.f;
    float4 b0 = *(const float4*)(bias + sub * 8);
    float4 b1 = *(const float4*)(bias + sub * 8 + 4);
    float* op = out + (size_t)n * CH + sub * 8;
    op[0] = fmaf(a0.x, dinv, b0.x);
    op[1] = fmaf(a0.y, dinv, b0.y);
    op[2] = fmaf(a0.z, dinv, b0.z);
    op[3] = fmaf(a0.w, dinv, b0.w);
    op[4] = fmaf(a1.x, dinv, b1.x);
    op[5] = fmaf(a1.y, dinv, b1.y);
    op[6] = fmaf(a1.z, dinv, b1.z);
    op[7] = fmaf(a1.w, dinv, b1.w);
}

// ---------------- launch: fork GEMM || CSR-build, join before gathers --------
extern "C" void kernel_launch(void* const* d_in, const int* in_sizes, int n_in,
                              void* d_out, int out_size) {
    const float* x      = (const float*)d_in[0];     // [50000,128] f32
    const int*   he     = (const int*)d_in[1];       // [2,800000] int32
    const float* attn_w = (const float*)d_in[2];     // [1,128]
    const float* attn_b = (const float*)d_in[3];     // [1]
    const float* lin_w  = (const float*)d_in[4];     // [128,128]
    const float* bias   = (const float*)d_in[5];     // [128]
    float*       out    = (float*)d_out;             // [50000,128]

    static cudaStream_t s2 = nullptr;
    static cudaEvent_t  evF = nullptr, evJ = nullptr;
    if (s2 == nullptr) {
        cudaStreamCreateWithFlags(&s2, cudaStreamNonBlocking);
        cudaEventCreateWithFlags(&evF, cudaEventDisableTiming);
        cudaEventCreateWithFlags(&evJ, cudaEventDisableTiming);
    }

    // fork: CSR-build chain on s2
    cudaEventRecord(evF, 0);
    cudaStreamWaitEvent(s2, evF, 0);

    k_zero<<<NBE, 256, 0, s2>>>();
    const int nb = (NNZV + 255) / 256;
    k_hist<<<nb, 256, 0, s2>>>(he);
    k_scanA<<<TOTB, 256, 0, s2>>>();
    k_scanC<<<TOTB, 256, 0, s2>>>();
    k_fill<<<nb, 256, 0, s2>>>(he);
    cudaEventRecord(evJ, s2);

    // GEMM on the main (legacy) stream, concurrent with CSR build
    const int smem = (128 * 132 + 128 * 34) * (int)sizeof(float);  // ~85 KB
    cudaFuncSetAttribute(k_gemm, cudaFuncAttributeMaxDynamicSharedMemorySize, smem);
    k_gemm<<<296, 128, smem>>>(x, lin_w, attn_w, attn_b);

    // join, then gathers
    cudaStreamWaitEvent(0, evJ, 0);
    const int gb = ((NE / 2) * 32 + 255) / 256;
    k_gather_edge<<<gb, 256>>>();
    k_gather_node<<<gb, 256>>>(out, bias);
}